// round 6
// baseline (speedup 1.0000x reference)
#include <cuda_runtime.h>
#include <cuda_fp16.h>
#include <cstdint>

// Problem shape (fixed by dataset)
#define M_TOKENS 16384
#define K_DIM    2048
#define N_DIM    2048
#define EPS      1e-7f

// GEMM tiling
#define BM 128
#define BN 256
#define BK 64
#define NSTAGE 4
#define SROW 80                      // padded smem row pitch (bytes), 16B-aligned
#define STAGE_B ((BM + BN) * SROW)   // 30720 bytes per stage
#define NKT (K_DIM / BK)             // 32

// Scratch (device globals: no allocations allowed)
__device__ int8_t g_q[(size_t)M_TOKENS * K_DIM];
__device__ int8_t g_w[(size_t)N_DIM * K_DIM];
__device__ float  g_scales[M_TOKENS];

// ---------------------------------------------------------------------------
// Kernel 0: pack int32-marshalled weights to int8.
// ---------------------------------------------------------------------------
__global__ __launch_bounds__(256) void pack_w_kernel(const int* __restrict__ w32) {
    const int idx = blockIdx.x * blockDim.x + threadIdx.x;
    int4 v = reinterpret_cast<const int4*>(w32)[idx];
    char4 c = make_char4((char)v.x, (char)v.y, (char)v.z, (char)v.w);
    reinterpret_cast<char4*>(g_w)[idx] = c;
}

// ---------------------------------------------------------------------------
// Kernel 1: per-token dynamic int8 quantization (validated).
// ---------------------------------------------------------------------------
__global__ __launch_bounds__(256) void quant_kernel(const float* __restrict__ x) {
    const int token = blockIdx.x;
    const int tid = threadIdx.x;
    const int lane = tid & 31;
    const int warp = tid >> 5;

    const float4* xr = reinterpret_cast<const float4*>(x + (size_t)token * K_DIM);
    float4 v0 = xr[tid * 2 + 0];
    float4 v1 = xr[tid * 2 + 1];

    float m = fabsf(v0.x);
    m = fmaxf(m, fabsf(v0.y)); m = fmaxf(m, fabsf(v0.z)); m = fmaxf(m, fabsf(v0.w));
    m = fmaxf(m, fabsf(v1.x)); m = fmaxf(m, fabsf(v1.y));
    m = fmaxf(m, fabsf(v1.z)); m = fmaxf(m, fabsf(v1.w));

    #pragma unroll
    for (int off = 16; off > 0; off >>= 1)
        m = fmaxf(m, __shfl_xor_sync(0xFFFFFFFFu, m, off));

    __shared__ float wmax[8];
    if (lane == 0) wmax[warp] = m;
    __syncthreads();
    if (warp == 0) {
        float t = (lane < 8) ? wmax[lane] : 0.0f;
        #pragma unroll
        for (int off = 4; off > 0; off >>= 1)
            t = fmaxf(t, __shfl_xor_sync(0xFFFFFFFFu, t, off));
        if (lane == 0) wmax[0] = t;
    }
    __syncthreads();
    const float absmax = wmax[0];
    const float scale = fmaxf(absmax, EPS) / 127.0f;

    if (tid == 0) g_scales[token] = scale;

    const float inv = 1.0f / scale;
    float vals[8] = {v0.x, v0.y, v0.z, v0.w, v1.x, v1.y, v1.z, v1.w};
    uint32_t p0 = 0, p1 = 0;
    #pragma unroll
    for (int i = 0; i < 4; i++) {
        float q = rintf(vals[i] * inv);
        q = fminf(fmaxf(q, -128.0f), 127.0f);
        int qi = (int)q;
        p0 |= ((uint32_t)(qi & 0xFF)) << (8 * i);
    }
    #pragma unroll
    for (int i = 0; i < 4; i++) {
        float q = rintf(vals[4 + i] * inv);
        q = fminf(fmaxf(q, -128.0f), 127.0f);
        int qi = (int)q;
        p1 |= ((uint32_t)(qi & 0xFF)) << (8 * i);
    }
    int2 packed = make_int2((int)p0, (int)p1);
    *reinterpret_cast<int2*>(g_q + (size_t)token * K_DIM + tid * 8) = packed;
}

// ---------------------------------------------------------------------------
// Kernel 2: int8 GEMM, 128x256 CTA tile, 4-stage cp.async, ldmatrix fragments.
// ---------------------------------------------------------------------------
__device__ __forceinline__ void cp16s(uint32_t saddr, const int8_t* g) {
    asm volatile("cp.async.cg.shared.global [%0], [%1], 16;\n" :: "r"(saddr), "l"(g));
}
__device__ __forceinline__ void ldsm4(uint32_t& r0, uint32_t& r1, uint32_t& r2, uint32_t& r3,
                                      uint32_t addr) {
    asm volatile("ldmatrix.sync.aligned.m8n8.x4.shared.b16 {%0,%1,%2,%3}, [%4];"
                 : "=r"(r0), "=r"(r1), "=r"(r2), "=r"(r3) : "r"(addr));
}

__global__ __launch_bounds__(256, 1) void gemm_kernel(const float* __restrict__ w_scale,
                                                      const float* __restrict__ bias,
                                                      float* __restrict__ out) {
    extern __shared__ char smem[];
    const uint32_t sbase = (uint32_t)__cvta_generic_to_shared(smem);

    const int tid = threadIdx.x;
    const int lane = tid & 31;
    const int warp = tid >> 5;
    const int warpM = warp >> 2;   // 0..1  (64 rows each)
    const int warpN = warp & 3;    // 0..3  (64 cols each)
    const int g = lane >> 2;       // 0..7
    const int tg = lane & 3;       // 0..3

    const int m0 = blockIdx.y * BM;
    const int n0 = blockIdx.x * BN;

    const int8_t* Ag = g_q + (size_t)m0 * K_DIM;
    const int8_t* Bg = g_w + (size_t)n0 * K_DIM;

    int acc[4][8][4];
    #pragma unroll
    for (int mi = 0; mi < 4; mi++)
        #pragma unroll
        for (int ni = 0; ni < 8; ni++)
            #pragma unroll
            for (int r = 0; r < 4; r++) acc[mi][ni][r] = 0;

    // --- per-stage cp.async issue (A: 512 x 16B, B: 1024 x 16B) ---
    auto issue_stage = [&](int stage, int k0) {
        const uint32_t aS = sbase + stage * STAGE_B;
        const uint32_t bS = aS + BM * SROW;
        #pragma unroll
        for (int it = 0; it < 2; it++) {
            int c = tid + it * 256;          // 0..511
            int r = c >> 2, kc = (c & 3) * 16;
            cp16s(aS + r * SROW + kc, Ag + (size_t)r * K_DIM + k0 + kc);
        }
        #pragma unroll
        for (int it = 0; it < 4; it++) {
            int c = tid + it * 256;          // 0..1023
            int r = c >> 2, kc = (c & 3) * 16;
            cp16s(bS + r * SROW + kc, Bg + (size_t)r * K_DIM + k0 + kc);
        }
    };

    // Prologue: stages 0..2
    #pragma unroll
    for (int s = 0; s < NSTAGE - 1; s++) {
        issue_stage(s, s * BK);
        asm volatile("cp.async.commit_group;\n");
    }

    // precomputed ldmatrix lane-address components
    const int aRow = warpM * 64 + (lane & 7) + ((lane >> 3) & 1) * 8;   // + mi*16
    const int aKof = (lane >> 4) * 16;                                  // + ks*32
    const int bRow = warpN * 64 + (lane >> 4) * 8 + (lane & 7);         // + j2*16
    const int bKof = ((lane >> 3) & 1) * 16;                            // + ks*32

    for (int kt = 0; kt < NKT; kt++) {
        asm volatile("cp.async.wait_group 2;\n");
        __syncthreads();

        const int pf = kt + NSTAGE - 1;
        if (pf < NKT) issue_stage(pf & 3, pf * BK);
        asm volatile("cp.async.commit_group;\n");

        const uint32_t aS = sbase + (kt & 3) * STAGE_B;
        const uint32_t bS = aS + BM * SROW;

        #pragma unroll
        for (int ks = 0; ks < 2; ks++) {
            const int k0 = ks * 32;
            uint32_t afr[4][4];
            #pragma unroll
            for (int mi = 0; mi < 4; mi++) {
                uint32_t addr = aS + (aRow + mi * 16) * SROW + k0 + aKof;
                ldsm4(afr[mi][0], afr[mi][1], afr[mi][2], afr[mi][3], addr);
            }
            uint32_t bfr[8][2];
            #pragma unroll
            for (int j2 = 0; j2 < 4; j2++) {
                uint32_t b0, b1, b2, b3;
                uint32_t addr = bS + (bRow + j2 * 16) * SROW + k0 + bKof;
                ldsm4(b0, b1, b2, b3, addr);
                bfr[2 * j2][0] = b0; bfr[2 * j2][1] = b1;
                bfr[2 * j2 + 1][0] = b2; bfr[2 * j2 + 1][1] = b3;
            }
            #pragma unroll
            for (int mi = 0; mi < 4; mi++)
                #pragma unroll
                for (int ni = 0; ni < 8; ni++) {
                    asm volatile(
                        "mma.sync.aligned.m16n8k32.row.col.s32.s8.s8.s32 "
                        "{%0,%1,%2,%3}, {%4,%5,%6,%7}, {%8,%9}, {%0,%1,%2,%3};\n"
                        : "+r"(acc[mi][ni][0]), "+r"(acc[mi][ni][1]),
                          "+r"(acc[mi][ni][2]), "+r"(acc[mi][ni][3])
                        : "r"(afr[mi][0]), "r"(afr[mi][1]), "r"(afr[mi][2]), "r"(afr[mi][3]),
                          "r"(bfr[ni][0]), "r"(bfr[ni][1]));
                }
        }
    }

    // Epilogue: dequant + bias, round through fp16, store fp32 (validated).
    #pragma unroll
    for (int mi = 0; mi < 4; mi++) {
        const int r0 = m0 + warpM * 64 + mi * 16 + g;
        const float s0 = g_scales[r0];
        const float s1 = g_scales[r0 + 8];
        #pragma unroll
        for (int ni = 0; ni < 8; ni++) {
            const int c = n0 + warpN * 64 + ni * 8 + tg * 2;
            const float w0 = w_scale[c];
            const float w1 = w_scale[c + 1];
            const float b0 = bias[c];
            const float b1 = bias[c + 1];

            float2 o0, o1;
            o0.x = __half2float(__float2half_rn((float)acc[mi][ni][0] * s0 * w0 + b0));
            o0.y = __half2float(__float2half_rn((float)acc[mi][ni][1] * s0 * w1 + b1));
            o1.x = __half2float(__float2half_rn((float)acc[mi][ni][2] * s1 * w0 + b0));
            o1.y = __half2float(__float2half_rn((float)acc[mi][ni][3] * s1 * w1 + b1));

            *reinterpret_cast<float2*>(out + (size_t)r0 * N_DIM + c) = o0;
            *reinterpret_cast<float2*>(out + (size_t)(r0 + 8) * N_DIM + c) = o1;
        }
    }
}

extern "C" void kernel_launch(void* const* d_in, const int* in_sizes, int n_in,
                              void* d_out, int out_size) {
    const float* x       = (const float*)d_in[0];
    const int*   weight  = (const int*)d_in[1];   // int8 marshalled as int32
    const float* w_scale = (const float*)d_in[2];
    const float* bias    = (const float*)d_in[3];
    float* out = (float*)d_out;

    pack_w_kernel<<<(N_DIM * K_DIM / 4) / 256, 256>>>(weight);
    quant_kernel<<<M_TOKENS, 256>>>(x);

    const int smem_bytes = NSTAGE * STAGE_B;  // 122880
    cudaFuncSetAttribute(gemm_kernel, cudaFuncAttributeMaxDynamicSharedMemorySize, smem_bytes);
    dim3 grid(N_DIM / BN, M_TOKENS / BM);     // (8, 128)
    gemm_kernel<<<grid, 256, smem_bytes>>>(w_scale, bias, out);
}

// round 7
// speedup vs baseline: 1.0674x; 1.0674x over previous
#include <cuda_runtime.h>
#include <cuda_fp16.h>
#include <cstdint>

// Problem shape (fixed by dataset)
#define M_TOKENS 16384
#define K_DIM    2048
#define N_DIM    2048
#define EPS      1e-7f

// GEMM tiling
#define BM 128
#define BN 128
#define BK 64
#define NSTAGE 4
#define SROW 80                      // padded smem row pitch (bytes), 16B-aligned
#define STAGE_B ((BM + BN) * SROW)   // 20480 bytes per stage
#define NKT (K_DIM / BK)             // 32

// Scratch (device globals: no allocations allowed)
__device__ int8_t g_q[(size_t)M_TOKENS * K_DIM];
__device__ int8_t g_w[(size_t)N_DIM * K_DIM];
__device__ float  g_scales[M_TOKENS];

// ---------------------------------------------------------------------------
// Kernel 0: pack int32-marshalled weights to int8.
// ---------------------------------------------------------------------------
__global__ __launch_bounds__(256) void pack_w_kernel(const int* __restrict__ w32) {
    const int idx = blockIdx.x * blockDim.x + threadIdx.x;
    int4 v = reinterpret_cast<const int4*>(w32)[idx];
    char4 c = make_char4((char)v.x, (char)v.y, (char)v.z, (char)v.w);
    reinterpret_cast<char4*>(g_w)[idx] = c;
}

// ---------------------------------------------------------------------------
// Kernel 1: per-token dynamic int8 quantization (validated).
// ---------------------------------------------------------------------------
__global__ __launch_bounds__(256) void quant_kernel(const float* __restrict__ x) {
    const int token = blockIdx.x;
    const int tid = threadIdx.x;
    const int lane = tid & 31;
    const int warp = tid >> 5;

    const float4* xr = reinterpret_cast<const float4*>(x + (size_t)token * K_DIM);
    float4 v0 = xr[tid * 2 + 0];
    float4 v1 = xr[tid * 2 + 1];

    float m = fabsf(v0.x);
    m = fmaxf(m, fabsf(v0.y)); m = fmaxf(m, fabsf(v0.z)); m = fmaxf(m, fabsf(v0.w));
    m = fmaxf(m, fabsf(v1.x)); m = fmaxf(m, fabsf(v1.y));
    m = fmaxf(m, fabsf(v1.z)); m = fmaxf(m, fabsf(v1.w));

    #pragma unroll
    for (int off = 16; off > 0; off >>= 1)
        m = fmaxf(m, __shfl_xor_sync(0xFFFFFFFFu, m, off));

    __shared__ float wmax[8];
    if (lane == 0) wmax[warp] = m;
    __syncthreads();
    if (warp == 0) {
        float t = (lane < 8) ? wmax[lane] : 0.0f;
        #pragma unroll
        for (int off = 4; off > 0; off >>= 1)
            t = fmaxf(t, __shfl_xor_sync(0xFFFFFFFFu, t, off));
        if (lane == 0) wmax[0] = t;
    }
    __syncthreads();
    const float absmax = wmax[0];
    const float scale = fmaxf(absmax, EPS) / 127.0f;

    if (tid == 0) g_scales[token] = scale;

    const float inv = 1.0f / scale;
    float vals[8] = {v0.x, v0.y, v0.z, v0.w, v1.x, v1.y, v1.z, v1.w};
    uint32_t p0 = 0, p1 = 0;
    #pragma unroll
    for (int i = 0; i < 4; i++) {
        float q = rintf(vals[i] * inv);
        q = fminf(fmaxf(q, -128.0f), 127.0f);
        int qi = (int)q;
        p0 |= ((uint32_t)(qi & 0xFF)) << (8 * i);
    }
    #pragma unroll
    for (int i = 0; i < 4; i++) {
        float q = rintf(vals[4 + i] * inv);
        q = fminf(fmaxf(q, -128.0f), 127.0f);
        int qi = (int)q;
        p1 |= ((uint32_t)(qi & 0xFF)) << (8 * i);
    }
    int2 packed = make_int2((int)p0, (int)p1);
    *reinterpret_cast<int2*>(g_q + (size_t)token * K_DIM + tid * 8) = packed;
}

// ---------------------------------------------------------------------------
// Kernel 2: int8 GEMM, 128x128 CTA tile, 4-stage cp.async, ldmatrix fragments,
// 2 CTAs/SM for cross-CTA latency hiding.
// ---------------------------------------------------------------------------
__device__ __forceinline__ void cp16s(uint32_t saddr, const int8_t* g) {
    asm volatile("cp.async.cg.shared.global [%0], [%1], 16;\n" :: "r"(saddr), "l"(g));
}
__device__ __forceinline__ void ldsm4(uint32_t& r0, uint32_t& r1, uint32_t& r2, uint32_t& r3,
                                      uint32_t addr) {
    asm volatile("ldmatrix.sync.aligned.m8n8.x4.shared.b16 {%0,%1,%2,%3}, [%4];"
                 : "=r"(r0), "=r"(r1), "=r"(r2), "=r"(r3) : "r"(addr));
}

__global__ __launch_bounds__(256, 2) void gemm_kernel(const float* __restrict__ w_scale,
                                                      const float* __restrict__ bias,
                                                      float* __restrict__ out) {
    extern __shared__ char smem[];
    const uint32_t sbase = (uint32_t)__cvta_generic_to_shared(smem);

    const int tid = threadIdx.x;
    const int lane = tid & 31;
    const int warp = tid >> 5;
    const int warpM = warp >> 2;   // 0..1  (64 rows each)
    const int warpN = warp & 3;    // 0..3  (32 cols each)
    const int g = lane >> 2;       // 0..7
    const int tg = lane & 3;       // 0..3

    const int m0 = blockIdx.y * BM;
    const int n0 = blockIdx.x * BN;

    const int8_t* Ag = g_q + (size_t)m0 * K_DIM;
    const int8_t* Bg = g_w + (size_t)n0 * K_DIM;

    int acc[4][4][4];
    #pragma unroll
    for (int mi = 0; mi < 4; mi++)
        #pragma unroll
        for (int ni = 0; ni < 4; ni++)
            #pragma unroll
            for (int r = 0; r < 4; r++) acc[mi][ni][r] = 0;

    // --- per-stage cp.async issue (A: 512 x 16B, B: 512 x 16B) ---
    auto issue_stage = [&](int stage, int k0) {
        const uint32_t aS = sbase + stage * STAGE_B;
        const uint32_t bS = aS + BM * SROW;
        #pragma unroll
        for (int it = 0; it < 2; it++) {
            int c = tid + it * 256;          // 0..511
            int r = c >> 2, kc = (c & 3) * 16;
            cp16s(aS + r * SROW + kc, Ag + (size_t)r * K_DIM + k0 + kc);
            cp16s(bS + r * SROW + kc, Bg + (size_t)r * K_DIM + k0 + kc);
        }
    };

    // Prologue: stages 0..2
    #pragma unroll
    for (int s = 0; s < NSTAGE - 1; s++) {
        issue_stage(s, s * BK);
        asm volatile("cp.async.commit_group;\n");
    }

    // ldmatrix lane-address components (validated layout in R5)
    const int aRow = warpM * 64 + (lane & 7) + ((lane >> 3) & 1) * 8;   // + mi*16
    const int aKof = (lane >> 4) * 16;                                  // + ks*32
    const int bRow = warpN * 32 + (lane >> 4) * 8 + (lane & 7);         // + j2*16
    const int bKof = ((lane >> 3) & 1) * 16;                            // + ks*32

    for (int kt = 0; kt < NKT; kt++) {
        asm volatile("cp.async.wait_group 2;\n");
        __syncthreads();

        const int pf = kt + NSTAGE - 1;
        if (pf < NKT) issue_stage(pf & 3, pf * BK);
        asm volatile("cp.async.commit_group;\n");

        const uint32_t aS = sbase + (kt & 3) * STAGE_B;
        const uint32_t bS = aS + BM * SROW;

        #pragma unroll
        for (int ks = 0; ks < 2; ks++) {
            const int k0 = ks * 32;
            uint32_t afr[4][4];
            #pragma unroll
            for (int mi = 0; mi < 4; mi++) {
                uint32_t addr = aS + (aRow + mi * 16) * SROW + k0 + aKof;
                ldsm4(afr[mi][0], afr[mi][1], afr[mi][2], afr[mi][3], addr);
            }
            uint32_t bfr[4][2];
            #pragma unroll
            for (int j2 = 0; j2 < 2; j2++) {
                uint32_t b0, b1, b2, b3;
                uint32_t addr = bS + (bRow + j2 * 16) * SROW + k0 + bKof;
                ldsm4(b0, b1, b2, b3, addr);
                bfr[2 * j2][0] = b0; bfr[2 * j2][1] = b1;
                bfr[2 * j2 + 1][0] = b2; bfr[2 * j2 + 1][1] = b3;
            }
            #pragma unroll
            for (int mi = 0; mi < 4; mi++)
                #pragma unroll
                for (int ni = 0; ni < 4; ni++) {
                    asm volatile(
                        "mma.sync.aligned.m16n8k32.row.col.s32.s8.s8.s32 "
                        "{%0,%1,%2,%3}, {%4,%5,%6,%7}, {%8,%9}, {%0,%1,%2,%3};\n"
                        : "+r"(acc[mi][ni][0]), "+r"(acc[mi][ni][1]),
                          "+r"(acc[mi][ni][2]), "+r"(acc[mi][ni][3])
                        : "r"(afr[mi][0]), "r"(afr[mi][1]), "r"(afr[mi][2]), "r"(afr[mi][3]),
                          "r"(bfr[ni][0]), "r"(bfr[ni][1]));
                }
        }
    }

    // Epilogue: dequant + bias, round through fp16, store fp32 (validated).
    #pragma unroll
    for (int mi = 0; mi < 4; mi++) {
        const int r0 = m0 + warpM * 64 + mi * 16 + g;
        const float s0 = g_scales[r0];
        const float s1 = g_scales[r0 + 8];
        #pragma unroll
        for (int ni = 0; ni < 4; ni++) {
            const int c = n0 + warpN * 32 + ni * 8 + tg * 2;
            const float w0 = w_scale[c];
            const float w1 = w_scale[c + 1];
            const float b0 = bias[c];
            const float b1 = bias[c + 1];

            float2 o0, o1;
            o0.x = __half2float(__float2half_rn((float)acc[mi][ni][0] * s0 * w0 + b0));
            o0.y = __half2float(__float2half_rn((float)acc[mi][ni][1] * s0 * w1 + b1));
            o1.x = __half2float(__float2half_rn((float)acc[mi][ni][2] * s1 * w0 + b0));
            o1.y = __half2float(__float2half_rn((float)acc[mi][ni][3] * s1 * w1 + b1));

            *reinterpret_cast<float2*>(out + (size_t)r0 * N_DIM + c) = o0;
            *reinterpret_cast<float2*>(out + (size_t)(r0 + 8) * N_DIM + c) = o1;
        }
    }
}

extern "C" void kernel_launch(void* const* d_in, const int* in_sizes, int n_in,
                              void* d_out, int out_size) {
    const float* x       = (const float*)d_in[0];
    const int*   weight  = (const int*)d_in[1];   // int8 marshalled as int32
    const float* w_scale = (const float*)d_in[2];
    const float* bias    = (const float*)d_in[3];
    float* out = (float*)d_out;

    pack_w_kernel<<<(N_DIM * K_DIM / 4) / 256, 256>>>(weight);
    quant_kernel<<<M_TOKENS, 256>>>(x);

    const int smem_bytes = NSTAGE * STAGE_B;  // 81920
    cudaFuncSetAttribute(gemm_kernel, cudaFuncAttributeMaxDynamicSharedMemorySize, smem_bytes);
    dim3 grid(N_DIM / BN, M_TOKENS / BM);     // (16, 128)
    gemm_kernel<<<grid, 256, smem_bytes>>>(w_scale, bias, out);
}

// round 8
// speedup vs baseline: 1.4404x; 1.3495x over previous
#include <cuda_runtime.h>
#include <cuda_fp16.h>
#include <cstdint>

// Problem shape (fixed by dataset)
#define M_TOKENS 16384
#define K_DIM    2048
#define N_DIM    2048
#define EPS      1e-7f

// Shared tiling constants
#define BM 128
#define BN 128
#define NSTAGE 4
#define SROW 80                      // padded smem row pitch (bytes), 16B-aligned
#define STAGE_B ((BM + BN) * SROW)   // 20480 bytes per stage

// int8 path: BK 64 int8 elems = 64 B/row; 32 kt
#define NKT_I8 32
// fp16 path: 32 fp16 elems = 64 B/row; 64 kt
#define NKT_F16 64

// Scratch (device globals: no allocations allowed)
__device__ int8_t g_q[(size_t)M_TOKENS * K_DIM];       // int8 activations
__device__ __half g_qh[(size_t)M_TOKENS * K_DIM];      // fp16 activations
__device__ int8_t g_w[(size_t)N_DIM * K_DIM];          // int8 weights
__device__ __half g_wh[(size_t)N_DIM * K_DIM];         // fp16 weights
__device__ float  g_scales[M_TOKENS];

// ---------------------------------------------------------------------------
// Kernel 0: pack int32-marshalled weights to int8 AND fp16.
// ---------------------------------------------------------------------------
__global__ __launch_bounds__(256) void pack_w_kernel(const int* __restrict__ w32) {
    const int idx = blockIdx.x * blockDim.x + threadIdx.x;
    int4 v = reinterpret_cast<const int4*>(w32)[idx];
    char4 c = make_char4((char)v.x, (char)v.y, (char)v.z, (char)v.w);
    reinterpret_cast<char4*>(g_w)[idx] = c;
    __half2 h0 = __halves2half2(__int2half_rn(v.x), __int2half_rn(v.y));
    __half2 h1 = __halves2half2(__int2half_rn(v.z), __int2half_rn(v.w));
    uint2 hp = make_uint2(*(uint32_t*)&h0, *(uint32_t*)&h1);
    reinterpret_cast<uint2*>(g_wh)[idx] = hp;
}

// ---------------------------------------------------------------------------
// Kernel 1: per-token dynamic int8 quantization, dual int8+fp16 output.
// ---------------------------------------------------------------------------
__global__ __launch_bounds__(256) void quant_kernel(const float* __restrict__ x) {
    const int token = blockIdx.x;
    const int tid = threadIdx.x;
    const int lane = tid & 31;
    const int warp = tid >> 5;

    const float4* xr = reinterpret_cast<const float4*>(x + (size_t)token * K_DIM);
    float4 v0 = xr[tid * 2 + 0];
    float4 v1 = xr[tid * 2 + 1];

    float m = fabsf(v0.x);
    m = fmaxf(m, fabsf(v0.y)); m = fmaxf(m, fabsf(v0.z)); m = fmaxf(m, fabsf(v0.w));
    m = fmaxf(m, fabsf(v1.x)); m = fmaxf(m, fabsf(v1.y));
    m = fmaxf(m, fabsf(v1.z)); m = fmaxf(m, fabsf(v1.w));

    #pragma unroll
    for (int off = 16; off > 0; off >>= 1)
        m = fmaxf(m, __shfl_xor_sync(0xFFFFFFFFu, m, off));

    __shared__ float wmax[8];
    if (lane == 0) wmax[warp] = m;
    __syncthreads();
    if (warp == 0) {
        float t = (lane < 8) ? wmax[lane] : 0.0f;
        #pragma unroll
        for (int off = 4; off > 0; off >>= 1)
            t = fmaxf(t, __shfl_xor_sync(0xFFFFFFFFu, t, off));
        if (lane == 0) wmax[0] = t;
    }
    __syncthreads();
    const float absmax = wmax[0];
    const float scale = fmaxf(absmax, EPS) / 127.0f;

    if (tid == 0) g_scales[token] = scale;

    const float inv = 1.0f / scale;
    float vals[8] = {v0.x, v0.y, v0.z, v0.w, v1.x, v1.y, v1.z, v1.w};
    int qv[8];
    #pragma unroll
    for (int i = 0; i < 8; i++) {
        float q = rintf(vals[i] * inv);
        q = fminf(fmaxf(q, -128.0f), 127.0f);
        qv[i] = (int)q;
    }
    uint32_t p0 = 0, p1 = 0;
    #pragma unroll
    for (int i = 0; i < 4; i++) p0 |= ((uint32_t)(qv[i] & 0xFF)) << (8 * i);
    #pragma unroll
    for (int i = 0; i < 4; i++) p1 |= ((uint32_t)(qv[4 + i] & 0xFF)) << (8 * i);
    *reinterpret_cast<int2*>(g_q + (size_t)token * K_DIM + tid * 8) = make_int2((int)p0, (int)p1);

    // fp16 copy (exact: |q| <= 127)
    uint4 hq;
    __half2 h;
    h = __halves2half2(__int2half_rn(qv[0]), __int2half_rn(qv[1])); hq.x = *(uint32_t*)&h;
    h = __halves2half2(__int2half_rn(qv[2]), __int2half_rn(qv[3])); hq.y = *(uint32_t*)&h;
    h = __halves2half2(__int2half_rn(qv[4]), __int2half_rn(qv[5])); hq.z = *(uint32_t*)&h;
    h = __halves2half2(__int2half_rn(qv[6]), __int2half_rn(qv[7])); hq.w = *(uint32_t*)&h;
    *reinterpret_cast<uint4*>(g_qh + (size_t)token * K_DIM + tid * 8) = hq;
}

// ---------------------------------------------------------------------------
// Common device helpers
// ---------------------------------------------------------------------------
__device__ __forceinline__ void cp16s(uint32_t saddr, const void* g) {
    asm volatile("cp.async.cg.shared.global [%0], [%1], 16;\n" :: "r"(saddr), "l"(g));
}
__device__ __forceinline__ void ldsm4(uint32_t& r0, uint32_t& r1, uint32_t& r2, uint32_t& r3,
                                      uint32_t addr) {
    asm volatile("ldmatrix.sync.aligned.m8n8.x4.shared.b16 {%0,%1,%2,%3}, [%4];"
                 : "=r"(r0), "=r"(r1), "=r"(r2), "=r"(r3) : "r"(addr));
}

// ---------------------------------------------------------------------------
// Kernel 2a: int8 GEMM for output columns [0, 1024). (validated R6 structure)
// ---------------------------------------------------------------------------
__global__ __launch_bounds__(256, 2) void gemm_i8_kernel(const float* __restrict__ w_scale,
                                                         const float* __restrict__ bias,
                                                         float* __restrict__ out) {
    extern __shared__ char smem[];
    const uint32_t sbase = (uint32_t)__cvta_generic_to_shared(smem);

    const int tid = threadIdx.x;
    const int lane = tid & 31;
    const int warp = tid >> 5;
    const int warpM = warp >> 2;
    const int warpN = warp & 3;
    const int g = lane >> 2;
    const int tg = lane & 3;

    const int m0 = blockIdx.y * BM;
    const int n0 = blockIdx.x * BN;           // 0..896

    const int8_t* Ag = g_q + (size_t)m0 * K_DIM;
    const int8_t* Bg = g_w + (size_t)n0 * K_DIM;

    int acc[4][4][4];
    #pragma unroll
    for (int mi = 0; mi < 4; mi++)
        #pragma unroll
        for (int ni = 0; ni < 4; ni++)
            #pragma unroll
            for (int r = 0; r < 4; r++) acc[mi][ni][r] = 0;

    auto issue_stage = [&](int stage, int k0) {
        const uint32_t aS = sbase + stage * STAGE_B;
        const uint32_t bS = aS + BM * SROW;
        #pragma unroll
        for (int it = 0; it < 2; it++) {
            int c = tid + it * 256;
            int r = c >> 2, kc = (c & 3) * 16;
            cp16s(aS + r * SROW + kc, Ag + (size_t)r * K_DIM + k0 + kc);
            cp16s(bS + r * SROW + kc, Bg + (size_t)r * K_DIM + k0 + kc);
        }
    };

    #pragma unroll
    for (int s = 0; s < NSTAGE - 1; s++) {
        issue_stage(s, s * 64);
        asm volatile("cp.async.commit_group;\n");
    }

    const int aRow = warpM * 64 + (lane & 7) + ((lane >> 3) & 1) * 8;
    const int aKof = (lane >> 4) * 16;
    const int bRow = warpN * 32 + (lane >> 4) * 8 + (lane & 7);
    const int bKof = ((lane >> 3) & 1) * 16;

    for (int kt = 0; kt < NKT_I8; kt++) {
        asm volatile("cp.async.wait_group 2;\n");
        __syncthreads();

        const int pf = kt + NSTAGE - 1;
        if (pf < NKT_I8) issue_stage(pf & 3, pf * 64);
        asm volatile("cp.async.commit_group;\n");

        const uint32_t aS = sbase + (kt & 3) * STAGE_B;
        const uint32_t bS = aS + BM * SROW;

        #pragma unroll
        for (int ks = 0; ks < 2; ks++) {
            const int k0 = ks * 32;
            uint32_t afr[4][4];
            #pragma unroll
            for (int mi = 0; mi < 4; mi++)
                ldsm4(afr[mi][0], afr[mi][1], afr[mi][2], afr[mi][3],
                      aS + (aRow + mi * 16) * SROW + k0 + aKof);
            uint32_t bfr[4][2];
            #pragma unroll
            for (int j2 = 0; j2 < 2; j2++) {
                uint32_t b0, b1, b2, b3;
                ldsm4(b0, b1, b2, b3, bS + (bRow + j2 * 16) * SROW + k0 + bKof);
                bfr[2 * j2][0] = b0; bfr[2 * j2][1] = b1;
                bfr[2 * j2 + 1][0] = b2; bfr[2 * j2 + 1][1] = b3;
            }
            #pragma unroll
            for (int mi = 0; mi < 4; mi++)
                #pragma unroll
                for (int ni = 0; ni < 4; ni++) {
                    asm volatile(
                        "mma.sync.aligned.m16n8k32.row.col.s32.s8.s8.s32 "
                        "{%0,%1,%2,%3}, {%4,%5,%6,%7}, {%8,%9}, {%0,%1,%2,%3};\n"
                        : "+r"(acc[mi][ni][0]), "+r"(acc[mi][ni][1]),
                          "+r"(acc[mi][ni][2]), "+r"(acc[mi][ni][3])
                        : "r"(afr[mi][0]), "r"(afr[mi][1]), "r"(afr[mi][2]), "r"(afr[mi][3]),
                          "r"(bfr[ni][0]), "r"(bfr[ni][1]));
                }
        }
    }

    #pragma unroll
    for (int mi = 0; mi < 4; mi++) {
        const int r0 = m0 + warpM * 64 + mi * 16 + g;
        const float s0 = g_scales[r0];
        const float s1 = g_scales[r0 + 8];
        #pragma unroll
        for (int ni = 0; ni < 4; ni++) {
            const int c = n0 + warpN * 32 + ni * 8 + tg * 2;
            const float w0 = w_scale[c], w1 = w_scale[c + 1];
            const float b0 = bias[c],    b1 = bias[c + 1];
            float2 o0, o1;
            o0.x = __half2float(__float2half_rn((float)acc[mi][ni][0] * s0 * w0 + b0));
            o0.y = __half2float(__float2half_rn((float)acc[mi][ni][1] * s0 * w1 + b1));
            o1.x = __half2float(__float2half_rn((float)acc[mi][ni][2] * s1 * w0 + b0));
            o1.y = __half2float(__float2half_rn((float)acc[mi][ni][3] * s1 * w1 + b1));
            *reinterpret_cast<float2*>(out + (size_t)r0 * N_DIM + c) = o0;
            *reinterpret_cast<float2*>(out + (size_t)(r0 + 8) * N_DIM + c) = o1;
        }
    }
}

// ---------------------------------------------------------------------------
// Kernel 2b: fp16 HMMA GEMM for output columns [1024, 2048).
// Byte-isomorphic to 2a: rows are 64 B (= 32 fp16), 64 kt iterations.
// fp32 accumulate of exact int products -> bit-identical to int8 path.
// ---------------------------------------------------------------------------
__global__ __launch_bounds__(256, 2) void gemm_f16_kernel(const float* __restrict__ w_scale,
                                                          const float* __restrict__ bias,
                                                          float* __restrict__ out) {
    extern __shared__ char smem[];
    const uint32_t sbase = (uint32_t)__cvta_generic_to_shared(smem);

    const int tid = threadIdx.x;
    const int lane = tid & 31;
    const int warp = tid >> 5;
    const int warpM = warp >> 2;
    const int warpN = warp & 3;
    const int g = lane >> 2;
    const int tg = lane & 3;

    const int m0 = blockIdx.y * BM;
    const int n0 = 1024 + blockIdx.x * BN;    // 1024..1920

    const __half* Ag = g_qh + (size_t)m0 * K_DIM;
    const __half* Bg = g_wh + (size_t)n0 * K_DIM;

    float acc[4][4][4];
    #pragma unroll
    for (int mi = 0; mi < 4; mi++)
        #pragma unroll
        for (int ni = 0; ni < 4; ni++)
            #pragma unroll
            for (int r = 0; r < 4; r++) acc[mi][ni][r] = 0.0f;

    // per stage: 256 rows x 64 B = 1024 x 16B segments
    auto issue_stage = [&](int stage, int ke) {   // ke = fp16 element offset in K
        const uint32_t aS = sbase + stage * STAGE_B;
        const uint32_t bS = aS + BM * SROW;
        #pragma unroll
        for (int it = 0; it < 2; it++) {
            int c = tid + it * 256;               // 0..511
            int r = c >> 2, kc = (c & 3) * 16;    // kc: byte offset 0..48
            cp16s(aS + r * SROW + kc, (const char*)(Ag + (size_t)r * K_DIM + ke) + kc);
            cp16s(bS + r * SROW + kc, (const char*)(Bg + (size_t)r * K_DIM + ke) + kc);
        }
    };

    #pragma unroll
    for (int s = 0; s < NSTAGE - 1; s++) {
        issue_stage(s, s * 32);
        asm volatile("cp.async.commit_group;\n");
    }

    const int aRow = warpM * 64 + (lane & 7) + ((lane >> 3) & 1) * 8;
    const int aKof = (lane >> 4) * 16;
    const int bRow = warpN * 32 + (lane >> 4) * 8 + (lane & 7);
    const int bKof = ((lane >> 3) & 1) * 16;

    for (int kt = 0; kt < NKT_F16; kt++) {
        asm volatile("cp.async.wait_group 2;\n");
        __syncthreads();

        const int pf = kt + NSTAGE - 1;
        if (pf < NKT_F16) issue_stage(pf & 3, pf * 32);
        asm volatile("cp.async.commit_group;\n");

        const uint32_t aS = sbase + (kt & 3) * STAGE_B;
        const uint32_t bS = aS + BM * SROW;

        #pragma unroll
        for (int ks = 0; ks < 2; ks++) {
            const int k0 = ks * 32;               // byte offset
            uint32_t afr[4][4];
            #pragma unroll
            for (int mi = 0; mi < 4; mi++)
                ldsm4(afr[mi][0], afr[mi][1], afr[mi][2], afr[mi][3],
                      aS + (aRow + mi * 16) * SROW + k0 + aKof);
            uint32_t bfr[4][2];
            #pragma unroll
            for (int j2 = 0; j2 < 2; j2++) {
                uint32_t b0, b1, b2, b3;
                ldsm4(b0, b1, b2, b3, bS + (bRow + j2 * 16) * SROW + k0 + bKof);
                bfr[2 * j2][0] = b0; bfr[2 * j2][1] = b1;
                bfr[2 * j2 + 1][0] = b2; bfr[2 * j2 + 1][1] = b3;
            }
            #pragma unroll
            for (int mi = 0; mi < 4; mi++)
                #pragma unroll
                for (int ni = 0; ni < 4; ni++) {
                    asm volatile(
                        "mma.sync.aligned.m16n8k16.row.col.f32.f16.f16.f32 "
                        "{%0,%1,%2,%3}, {%4,%5,%6,%7}, {%8,%9}, {%0,%1,%2,%3};\n"
                        : "+f"(acc[mi][ni][0]), "+f"(acc[mi][ni][1]),
                          "+f"(acc[mi][ni][2]), "+f"(acc[mi][ni][3])
                        : "r"(afr[mi][0]), "r"(afr[mi][1]), "r"(afr[mi][2]), "r"(afr[mi][3]),
                          "r"(bfr[ni][0]), "r"(bfr[ni][1]));
                }
        }
    }

    #pragma unroll
    for (int mi = 0; mi < 4; mi++) {
        const int r0 = m0 + warpM * 64 + mi * 16 + g;
        const float s0 = g_scales[r0];
        const float s1 = g_scales[r0 + 8];
        #pragma unroll
        for (int ni = 0; ni < 4; ni++) {
            const int c = n0 + warpN * 32 + ni * 8 + tg * 2;
            const float w0 = w_scale[c], w1 = w_scale[c + 1];
            const float b0 = bias[c],    b1 = bias[c + 1];
            float2 o0, o1;
            o0.x = __half2float(__float2half_rn(acc[mi][ni][0] * s0 * w0 + b0));
            o0.y = __half2float(__float2half_rn(acc[mi][ni][1] * s0 * w1 + b1));
            o1.x = __half2float(__float2half_rn(acc[mi][ni][2] * s1 * w0 + b0));
            o1.y = __half2float(__float2half_rn(acc[mi][ni][3] * s1 * w1 + b1));
            *reinterpret_cast<float2*>(out + (size_t)r0 * N_DIM + c) = o0;
            *reinterpret_cast<float2*>(out + (size_t)(r0 + 8) * N_DIM + c) = o1;
        }
    }
}

extern "C" void kernel_launch(void* const* d_in, const int* in_sizes, int n_in,
                              void* d_out, int out_size) {
    const float* x       = (const float*)d_in[0];
    const int*   weight  = (const int*)d_in[1];   // int8 marshalled as int32
    const float* w_scale = (const float*)d_in[2];
    const float* bias    = (const float*)d_in[3];
    float* out = (float*)d_out;

    pack_w_kernel<<<(N_DIM * K_DIM / 4) / 256, 256>>>(weight);
    quant_kernel<<<M_TOKENS, 256>>>(x);

    const int smem_bytes = NSTAGE * STAGE_B;  // 81920
    cudaFuncSetAttribute(gemm_i8_kernel, cudaFuncAttributeMaxDynamicSharedMemorySize, smem_bytes);
    cudaFuncSetAttribute(gemm_f16_kernel, cudaFuncAttributeMaxDynamicSharedMemorySize, smem_bytes);

    dim3 grid(8, M_TOKENS / BM);              // each half: 8 x 128 CTAs
    gemm_i8_kernel<<<grid, 256, smem_bytes>>>(w_scale, bias, out);
    gemm_f16_kernel<<<grid, 256, smem_bytes>>>(w_scale, bias, out);
}

// round 9
// speedup vs baseline: 2.5447x; 1.7666x over previous
#include <cuda_runtime.h>
#include <cuda_fp16.h>
#include <cstdint>

// Problem shape (fixed by dataset)
#define M_TOKENS 16384
#define K_DIM    2048
#define N_DIM    2048
#define EPS      1e-7f

// GEMM tiling: 128x128 CTA tile, K-chunk of 64 fp16 (128 B) per stage
#define BM 128
#define BN 128
#define NSTAGE 3
#define SROW 144                       // 128B payload + 16B pad (conflict-free)
#define STAGE_B ((BM + BN) * SROW)     // 36864 bytes
#define NKT 32                         // 2048 / 64

// Scratch (device globals)
__device__ __half g_qh[(size_t)M_TOKENS * K_DIM];  // fp16 activations (exact int8 values)
__device__ __half g_wh[(size_t)N_DIM * K_DIM];     // fp16 weights
__device__ float  g_scales[M_TOKENS];

// ---------------------------------------------------------------------------
// Kernel 0: pack int32-marshalled weights to fp16 (exact, |w| <= 127).
// ---------------------------------------------------------------------------
__global__ __launch_bounds__(256) void pack_w_kernel(const int* __restrict__ w32) {
    const int idx = blockIdx.x * blockDim.x + threadIdx.x;
    int4 v = reinterpret_cast<const int4*>(w32)[idx];
    __half2 h0 = __halves2half2(__int2half_rn(v.x), __int2half_rn(v.y));
    __half2 h1 = __halves2half2(__int2half_rn(v.z), __int2half_rn(v.w));
    uint2 hp = make_uint2(*(uint32_t*)&h0, *(uint32_t*)&h1);
    reinterpret_cast<uint2*>(g_wh)[idx] = hp;
}

// ---------------------------------------------------------------------------
// Kernel 1: per-token dynamic int8 quantization -> fp16 values (exact).
// ---------------------------------------------------------------------------
__global__ __launch_bounds__(256) void quant_kernel(const float* __restrict__ x) {
    const int token = blockIdx.x;
    const int tid = threadIdx.x;
    const int lane = tid & 31;
    const int warp = tid >> 5;

    const float4* xr = reinterpret_cast<const float4*>(x + (size_t)token * K_DIM);
    float4 v0 = xr[tid * 2 + 0];
    float4 v1 = xr[tid * 2 + 1];

    float m = fabsf(v0.x);
    m = fmaxf(m, fabsf(v0.y)); m = fmaxf(m, fabsf(v0.z)); m = fmaxf(m, fabsf(v0.w));
    m = fmaxf(m, fabsf(v1.x)); m = fmaxf(m, fabsf(v1.y));
    m = fmaxf(m, fabsf(v1.z)); m = fmaxf(m, fabsf(v1.w));

    #pragma unroll
    for (int off = 16; off > 0; off >>= 1)
        m = fmaxf(m, __shfl_xor_sync(0xFFFFFFFFu, m, off));

    __shared__ float wmax[8];
    if (lane == 0) wmax[warp] = m;
    __syncthreads();
    if (warp == 0) {
        float t = (lane < 8) ? wmax[lane] : 0.0f;
        #pragma unroll
        for (int off = 4; off > 0; off >>= 1)
            t = fmaxf(t, __shfl_xor_sync(0xFFFFFFFFu, t, off));
        if (lane == 0) wmax[0] = t;
    }
    __syncthreads();
    const float absmax = wmax[0];
    const float scale = fmaxf(absmax, EPS) / 127.0f;

    if (tid == 0) g_scales[token] = scale;

    const float inv = 1.0f / scale;
    float vals[8] = {v0.x, v0.y, v0.z, v0.w, v1.x, v1.y, v1.z, v1.w};
    int qv[8];
    #pragma unroll
    for (int i = 0; i < 8; i++) {
        float q = rintf(vals[i] * inv);
        q = fminf(fmaxf(q, -128.0f), 127.0f);
        qv[i] = (int)q;
    }
    uint4 hq;
    __half2 h;
    h = __halves2half2(__int2half_rn(qv[0]), __int2half_rn(qv[1])); hq.x = *(uint32_t*)&h;
    h = __halves2half2(__int2half_rn(qv[2]), __int2half_rn(qv[3])); hq.y = *(uint32_t*)&h;
    h = __halves2half2(__int2half_rn(qv[4]), __int2half_rn(qv[5])); hq.z = *(uint32_t*)&h;
    h = __halves2half2(__int2half_rn(qv[6]), __int2half_rn(qv[7])); hq.w = *(uint32_t*)&h;
    *reinterpret_cast<uint4*>(g_qh + (size_t)token * K_DIM + tid * 8) = hq;
}

// ---------------------------------------------------------------------------
// Kernel 2: fp16 HMMA GEMM, full N. 128x128 tile, 3-stage cp.async pipeline,
// 128B K-chunks (halved barrier count), ldmatrix fragments, 2 CTAs/SM.
// ---------------------------------------------------------------------------
__device__ __forceinline__ void cp16s(uint32_t saddr, const void* g) {
    asm volatile("cp.async.cg.shared.global [%0], [%1], 16;\n" :: "r"(saddr), "l"(g));
}
__device__ __forceinline__ void ldsm4(uint32_t& r0, uint32_t& r1, uint32_t& r2, uint32_t& r3,
                                      uint32_t addr) {
    asm volatile("ldmatrix.sync.aligned.m8n8.x4.shared.b16 {%0,%1,%2,%3}, [%4];"
                 : "=r"(r0), "=r"(r1), "=r"(r2), "=r"(r3) : "r"(addr));
}

__global__ __launch_bounds__(256, 2) void gemm_f16_kernel(const float* __restrict__ w_scale,
                                                          const float* __restrict__ bias,
                                                          float* __restrict__ out) {
    extern __shared__ char smem[];
    const uint32_t sbase = (uint32_t)__cvta_generic_to_shared(smem);

    const int tid = threadIdx.x;
    const int lane = tid & 31;
    const int warp = tid >> 5;
    const int warpM = warp >> 2;   // 0..1 (64 rows)
    const int warpN = warp & 3;    // 0..3 (32 cols)
    const int g = lane >> 2;
    const int tg = lane & 3;

    const int m0 = blockIdx.y * BM;
    const int n0 = blockIdx.x * BN;

    const __half* Ag = g_qh + (size_t)m0 * K_DIM;
    const __half* Bg = g_wh + (size_t)n0 * K_DIM;

    float acc[4][4][4];
    #pragma unroll
    for (int mi = 0; mi < 4; mi++)
        #pragma unroll
        for (int ni = 0; ni < 4; ni++)
            #pragma unroll
            for (int r = 0; r < 4; r++) acc[mi][ni][r] = 0.0f;

    // Per stage: 256 rows x 128 B = 2048 x 16B segments, 8 per thread.
    auto issue_stage = [&](int stage, int kb) {    // kb = K byte offset
        const uint32_t base = sbase + stage * STAGE_B;
        #pragma unroll
        for (int it = 0; it < 8; it++) {
            int c = tid + it * 256;                // 0..2047
            int r = c >> 3, kc = (c & 7) * 16;     // row 0..255, byte col 0..112
            const char* src = (r < BM)
                ? (const char*)(Ag + (size_t)r * K_DIM) + kb + kc
                : (const char*)(Bg + (size_t)(r - BM) * K_DIM) + kb + kc;
            cp16s(base + r * SROW + kc, src);
        }
    };

    #pragma unroll
    for (int s = 0; s < NSTAGE - 1; s++) {
        issue_stage(s, s * 128);
        asm volatile("cp.async.commit_group;\n");
    }

    // ldmatrix lane-address components (validated layout)
    const int aRow = warpM * 64 + (lane & 7) + ((lane >> 3) & 1) * 8;   // + mi*16
    const int aKof = (lane >> 4) * 16;                                  // + ks*32
    const int bRow = BM + warpN * 32 + (lane >> 4) * 8 + (lane & 7);    // + j2*16
    const int bKof = ((lane >> 3) & 1) * 16;                            // + ks*32

    int stage = 0;
    for (int kt = 0; kt < NKT; kt++) {
        asm volatile("cp.async.wait_group %0;\n" :: "n"(NSTAGE - 2));
        __syncthreads();

        const int pf = kt + NSTAGE - 1;
        int pstage = stage + NSTAGE - 1; if (pstage >= NSTAGE) pstage -= NSTAGE;
        if (pf < NKT) issue_stage(pstage, pf * 128);
        asm volatile("cp.async.commit_group;\n");

        const uint32_t base = sbase + stage * STAGE_B;

        #pragma unroll
        for (int ks = 0; ks < 4; ks++) {
            const int k0 = ks * 32;                 // byte offset in row
            uint32_t afr[4][4];
            #pragma unroll
            for (int mi = 0; mi < 4; mi++)
                ldsm4(afr[mi][0], afr[mi][1], afr[mi][2], afr[mi][3],
                      base + (aRow + mi * 16) * SROW + k0 + aKof);
            uint32_t bfr[4][2];
            #pragma unroll
            for (int j2 = 0; j2 < 2; j2++) {
                uint32_t b0, b1, b2, b3;
                ldsm4(b0, b1, b2, b3, base + (bRow + j2 * 16) * SROW + k0 + bKof);
                bfr[2 * j2][0] = b0; bfr[2 * j2][1] = b1;
                bfr[2 * j2 + 1][0] = b2; bfr[2 * j2 + 1][1] = b3;
            }
            #pragma unroll
            for (int mi = 0; mi < 4; mi++)
                #pragma unroll
                for (int ni = 0; ni < 4; ni++) {
                    asm volatile(
                        "mma.sync.aligned.m16n8k16.row.col.f32.f16.f16.f32 "
                        "{%0,%1,%2,%3}, {%4,%5,%6,%7}, {%8,%9}, {%0,%1,%2,%3};\n"
                        : "+f"(acc[mi][ni][0]), "+f"(acc[mi][ni][1]),
                          "+f"(acc[mi][ni][2]), "+f"(acc[mi][ni][3])
                        : "r"(afr[mi][0]), "r"(afr[mi][1]), "r"(afr[mi][2]), "r"(afr[mi][3]),
                          "r"(bfr[ni][0]), "r"(bfr[ni][1]));
                }
        }
        if (++stage == NSTAGE) stage = 0;
    }

    // Epilogue: dequant + bias, round through fp16, store fp32 (validated).
    #pragma unroll
    for (int mi = 0; mi < 4; mi++) {
        const int r0 = m0 + warpM * 64 + mi * 16 + g;
        const float s0 = g_scales[r0];
        const float s1 = g_scales[r0 + 8];
        #pragma unroll
        for (int ni = 0; ni < 4; ni++) {
            const int c = n0 + warpN * 32 + ni * 8 + tg * 2;
            const float w0 = w_scale[c], w1 = w_scale[c + 1];
            const float b0 = bias[c],    b1 = bias[c + 1];
            float2 o0, o1;
            o0.x = __half2float(__float2half_rn(acc[mi][ni][0] * s0 * w0 + b0));
            o0.y = __half2float(__float2half_rn(acc[mi][ni][1] * s0 * w1 + b1));
            o1.x = __half2float(__float2half_rn(acc[mi][ni][2] * s1 * w0 + b0));
            o1.y = __half2float(__float2half_rn(acc[mi][ni][3] * s1 * w1 + b1));
            *reinterpret_cast<float2*>(out + (size_t)r0 * N_DIM + c) = o0;
            *reinterpret_cast<float2*>(out + (size_t)(r0 + 8) * N_DIM + c) = o1;
        }
    }
}

extern "C" void kernel_launch(void* const* d_in, const int* in_sizes, int n_in,
                              void* d_out, int out_size) {
    const float* x       = (const float*)d_in[0];
    const int*   weight  = (const int*)d_in[1];   // int8 marshalled as int32
    const float* w_scale = (const float*)d_in[2];
    const float* bias    = (const float*)d_in[3];
    float* out = (float*)d_out;

    pack_w_kernel<<<(N_DIM * K_DIM / 4) / 256, 256>>>(weight);
    quant_kernel<<<M_TOKENS, 256>>>(x);

    const int smem_bytes = NSTAGE * STAGE_B;  // 110592
    cudaFuncSetAttribute(gemm_f16_kernel, cudaFuncAttributeMaxDynamicSharedMemorySize, smem_bytes);
    dim3 grid(N_DIM / BN, M_TOKENS / BM);     // (16, 128)
    gemm_f16_kernel<<<grid, 256, smem_bytes>>>(w_scale, bias, out);
}